// round 6
// baseline (speedup 1.0000x reference)
#include <cuda_runtime.h>
#include <cuda_fp16.h>
#include <cstdint>
#include <math.h>

#define NB 8192
#define ND 1024
#define BM 128
#define BN 128
#define BK 32
#define NBLK (NB / BM)                   /* 64 row/col blocks */
#define NTILES (NBLK * (NBLK + 1) / 2)   /* 2080 upper-tri tiles */
#define TPC 4                            /* tiles per CTA */
#define NCHUNKS (NTILES / TPC)           /* 520 CTAs */
#define THREADS 256
#define LDS_PAD 40                       /* halves per smem row (80B stride) */
#define KBLOCKS (ND / BK)                /* 32 */

// ---------------- static device scratch (no allocation) --------------------
__device__ __half g_h[NB * ND];             // normalized rows fp16 (16 MB)
__device__ float2 g_part[NB * NBLK];        // per-(row, colblock) top-2 (4 MB)

// ---------------- PTX helpers ----------------------------------------------
__device__ __forceinline__ uint32_t smem_u32(const void* p) {
    uint32_t a;
    asm("{ .reg .u64 t; cvta.to.shared.u64 t, %1; cvt.u32.u64 %0, t; }" : "=r"(a) : "l"(p));
    return a;
}
#define CP_ASYNC16(sm, gp) \
    asm volatile("cp.async.cg.shared.global [%0], [%1], 16;" :: "r"(sm), "l"(gp))
#define CP_COMMIT() asm volatile("cp.async.commit_group;" ::: "memory")
#define CP_WAIT1()  asm volatile("cp.async.wait_group 1;" ::: "memory")
#define CP_WAIT0()  asm volatile("cp.async.wait_group 0;" ::: "memory")
#define LDMATRIX_X4(r0, r1, r2, r3, addr) \
    asm volatile("ldmatrix.sync.aligned.m8n8.x4.shared.b16 {%0,%1,%2,%3}, [%4];" \
                 : "=r"(r0), "=r"(r1), "=r"(r2), "=r"(r3) : "r"(addr))
#define MMA16816(c, a, b0, b1) \
    asm volatile("mma.sync.aligned.m16n8k16.row.col.f32.f16.f16.f32 " \
                 "{%0,%1,%2,%3},{%4,%5,%6,%7},{%8,%9},{%0,%1,%2,%3};" \
                 : "+f"((c)[0]), "+f"((c)[1]), "+f"((c)[2]), "+f"((c)[3]) \
                 : "r"((a)[0]), "r"((a)[1]), "r"((a)[2]), "r"((a)[3]), "r"(b0), "r"(b1))

__device__ __forceinline__ void top2_merge(float2& t, float2 q) {
    if (q.x > t.x) { t.y = fmaxf(t.x, q.y); t.x = q.x; }
    else           { t.y = fmaxf(t.y, q.x); }
}
__device__ __forceinline__ void top2_push(float2& t, float v) {
    if (v > t.x) { t.y = t.x; t.x = v; }
    else if (v > t.y) { t.y = v; }
}
__device__ __forceinline__ void top2_shfl_merge(float2& t, int off) {
    float2 q;
    q.x = __shfl_xor_sync(0xFFFFFFFFu, t.x, off);
    q.y = __shfl_xor_sync(0xFFFFFFFFu, t.y, off);
    top2_merge(t, q);
}

// ---------------------------------------------------------------------------
// Kernel 1: L2-normalize rows, store fp16
// ---------------------------------------------------------------------------
__global__ void __launch_bounds__(256) normalize_kernel(const float* __restrict__ x) {
    int row = blockIdx.x;
    int t = threadIdx.x;
    const float4* xr = reinterpret_cast<const float4*>(x + (size_t)row * ND);
    float4 v = xr[t];
    float s = v.x * v.x + v.y * v.y + v.z * v.z + v.w * v.w;
    #pragma unroll
    for (int o = 16; o > 0; o >>= 1) s += __shfl_xor_sync(0xFFFFFFFFu, s, o);
    __shared__ float ws[8];
    int lane = t & 31, w = t >> 5;
    if (lane == 0) ws[w] = s;
    __syncthreads();
    if (t < 8) {
        float q = ws[t];
        #pragma unroll
        for (int o = 4; o > 0; o >>= 1) q += __shfl_xor_sync(0x000000FFu, q, o);
        if (t == 0) ws[0] = q;
    }
    __syncthreads();
    float inv = 1.0f / fmaxf(sqrtf(ws[0]), 1e-8f);
    __half2* oh = reinterpret_cast<__half2*>(g_h + (size_t)row * ND);
    oh[t * 2 + 0] = __floats2half2_rn(v.x * inv, v.y * inv);
    oh[t * 2 + 1] = __floats2half2_rn(v.z * inv, v.w * inv);
}

// ---------------------------------------------------------------------------
// Kernel 2: symmetric fp16 mma.sync — TPC upper-triangle tiles per CTA,
//           cross-tile prefetch, row-side + col-side top-2 per tile.
// ---------------------------------------------------------------------------
__global__ void __launch_bounds__(THREADS, 2) top2_sym_kernel() {
    __shared__ __half sA[2][BM * LDS_PAD];
    __shared__ __half sB[2][BN * LDS_PAD];
    __shared__ float2 s_redr[4][BM];   // row-side partials per N-warp
    __shared__ float2 s_redc[2][BN];   // col-side partials per M-warp

    // decode first upper-triangle tile (i, j), i <= j, from flat chunk start
    int i = 0, rem = blockIdx.x * TPC;
    while (rem >= NBLK - i) { rem -= NBLK - i; ++i; }
    int j = i + rem;

    const int tid = threadIdx.x;
    const int wid = tid >> 5, lane = tid & 31;
    const int warpM = wid >> 2, warpN = wid & 3;   // 2 x 4 warp grid

    const uint32_t sAu = smem_u32(&sA[0][0]);
    const uint32_t sBu = smem_u32(&sB[0][0]);
    const uint32_t BUFB = BM * LDS_PAD * 2;

    const int a_r = lane & 15;
    const int a_k = (lane >> 4) << 3;
    const int b_n = (lane & 7) + ((lane >> 4) << 3);
    const int b_k = ((lane >> 3) & 1) << 3;

    const int l_r0 = tid >> 2, l_k0 = tid & 3;
    const int l_r1 = (tid + 256) >> 2, l_k1 = (tid + 256) & 3;

    // per-thread constant parts of the smem store addresses
    const uint32_t sa0 = (l_r0 * LDS_PAD + l_k0 * 8) * 2;
    const uint32_t sa1 = (l_r1 * LDS_PAD + l_k1 * 8) * 2;

    // ---- prologue: tile 0 stage 0 ----
    {
        const int rs = i * BM, cs = j * BN;
        CP_ASYNC16(sAu + sa0, g_h + (size_t)(rs + l_r0) * ND + l_k0 * 8);
        CP_ASYNC16(sAu + sa1, g_h + (size_t)(rs + l_r1) * ND + l_k1 * 8);
        CP_ASYNC16(sBu + sa0, g_h + (size_t)(cs + l_r0) * ND + l_k0 * 8);
        CP_ASYNC16(sBu + sa1, g_h + (size_t)(cs + l_r1) * ND + l_k1 * 8);
        CP_COMMIT();
    }

    for (int t = 0; t < TPC; t++) {
        const int rowStart = i * BM;
        const int colStart = j * BN;
        // next tile coordinates (for cross-tile prefetch)
        int i2 = i, j2 = j + 1;
        if (j2 == NBLK) { i2 = i + 1; j2 = i2; }

        float acc[4][4][4];
        #pragma unroll
        for (int mi = 0; mi < 4; mi++)
            #pragma unroll
            for (int nj = 0; nj < 4; nj++)
                #pragma unroll
                for (int e = 0; e < 4; e++) acc[mi][nj][e] = 0.0f;

        for (int kb = 0; kb < KBLOCKS; kb++) {
            if (kb + 1 < KBLOCKS) {
                const int k0 = (kb + 1) * BK;
                const uint32_t bo = ((kb + 1) & 1) * BUFB;
                CP_ASYNC16(sAu + bo + sa0, g_h + (size_t)(rowStart + l_r0) * ND + k0 + l_k0 * 8);
                CP_ASYNC16(sAu + bo + sa1, g_h + (size_t)(rowStart + l_r1) * ND + k0 + l_k1 * 8);
                CP_ASYNC16(sBu + bo + sa0, g_h + (size_t)(colStart + l_r0) * ND + k0 + l_k0 * 8);
                CP_ASYNC16(sBu + bo + sa1, g_h + (size_t)(colStart + l_r1) * ND + k0 + l_k1 * 8);
                CP_COMMIT();
                CP_WAIT1();
            } else if (t + 1 < TPC) {
                // prefetch next tile's stage 0 into buffer 0 (hidden by epilogue)
                const int rs2 = i2 * BM, cs2 = j2 * BN;
                CP_ASYNC16(sAu + sa0, g_h + (size_t)(rs2 + l_r0) * ND + l_k0 * 8);
                CP_ASYNC16(sAu + sa1, g_h + (size_t)(rs2 + l_r1) * ND + l_k1 * 8);
                CP_ASYNC16(sBu + sa0, g_h + (size_t)(cs2 + l_r0) * ND + l_k0 * 8);
                CP_ASYNC16(sBu + sa1, g_h + (size_t)(cs2 + l_r1) * ND + l_k1 * 8);
                CP_COMMIT();
                CP_WAIT1();
            } else {
                CP_WAIT0();
            }
            __syncthreads();

            const uint32_t bo = (kb & 1) * BUFB;
            #pragma unroll
            for (int ks = 0; ks < 2; ks++) {
                uint32_t af[4][4];
                #pragma unroll
                for (int mi = 0; mi < 4; mi++) {
                    uint32_t addr = sAu + bo +
                        ((warpM * 64 + mi * 16 + a_r) * LDS_PAD + ks * 16 + a_k) * 2;
                    LDMATRIX_X4(af[mi][0], af[mi][1], af[mi][2], af[mi][3], addr);
                }
                uint32_t bf[2][4];
                #pragma unroll
                for (int nb = 0; nb < 2; nb++) {
                    uint32_t addr = sBu + bo +
                        ((warpN * 32 + nb * 16 + b_n) * LDS_PAD + ks * 16 + b_k) * 2;
                    LDMATRIX_X4(bf[nb][0], bf[nb][1], bf[nb][2], bf[nb][3], addr);
                }
                #pragma unroll
                for (int mi = 0; mi < 4; mi++)
                    #pragma unroll
                    for (int nj = 0; nj < 4; nj++)
                        MMA16816(acc[mi][nj], af[mi],
                                 bf[nj >> 1][(nj & 1) * 2], bf[nj >> 1][(nj & 1) * 2 + 1]);
            }
            __syncthreads();
        }

        // ---- mask diagonal in-place ----
        #pragma unroll
        for (int mi = 0; mi < 4; mi++) {
            const int row0 = rowStart + warpM * 64 + mi * 16 + (lane >> 2);
            #pragma unroll
            for (int nj = 0; nj < 4; nj++) {
                const int col0 = colStart + warpN * 32 + nj * 8 + (lane & 3) * 2;
                if (col0     == row0)     acc[mi][nj][0] = -2.0f;
                if (col0 + 1 == row0)     acc[mi][nj][1] = -2.0f;
                if (col0     == row0 + 8) acc[mi][nj][2] = -2.0f;
                if (col0 + 1 == row0 + 8) acc[mi][nj][3] = -2.0f;
            }
        }

        // ---- epilogue phase 1: row-side top-2 ----
        {
            float2 run[8];
            #pragma unroll
            for (int t2 = 0; t2 < 8; t2++) run[t2] = make_float2(-2.0f, -2.0f);
            #pragma unroll
            for (int mi = 0; mi < 4; mi++)
                #pragma unroll
                for (int nj = 0; nj < 4; nj++) {
                    top2_push(run[mi * 2 + 0], acc[mi][nj][0]);
                    top2_push(run[mi * 2 + 0], acc[mi][nj][1]);
                    top2_push(run[mi * 2 + 1], acc[mi][nj][2]);
                    top2_push(run[mi * 2 + 1], acc[mi][nj][3]);
                }
            #pragma unroll
            for (int t2 = 0; t2 < 8; t2++) {
                top2_shfl_merge(run[t2], 1);
                top2_shfl_merge(run[t2], 2);
            }
            if ((lane & 3) == 0) {
                #pragma unroll
                for (int mi = 0; mi < 4; mi++) {
                    int rbase = warpM * 64 + mi * 16 + (lane >> 2);
                    s_redr[warpN][rbase]     = run[mi * 2 + 0];
                    s_redr[warpN][rbase + 8] = run[mi * 2 + 1];
                }
            }
        }

        // ---- epilogue phase 2: col-side top-2 ----
        if (i != j) {
            float2 crun[8];
            #pragma unroll
            for (int t2 = 0; t2 < 8; t2++) crun[t2] = make_float2(-2.0f, -2.0f);
            #pragma unroll
            for (int nj = 0; nj < 4; nj++)
                #pragma unroll
                for (int mi = 0; mi < 4; mi++) {
                    top2_push(crun[nj * 2 + 0], acc[mi][nj][0]);
                    top2_push(crun[nj * 2 + 1], acc[mi][nj][1]);
                    top2_push(crun[nj * 2 + 0], acc[mi][nj][2]);
                    top2_push(crun[nj * 2 + 1], acc[mi][nj][3]);
                }
            #pragma unroll
            for (int t2 = 0; t2 < 8; t2++) {
                top2_shfl_merge(crun[t2], 4);
                top2_shfl_merge(crun[t2], 8);
                top2_shfl_merge(crun[t2], 16);
            }
            if (lane < 4) {
                #pragma unroll
                for (int nj = 0; nj < 4; nj++) {
                    int cbase = warpN * 32 + nj * 8 + lane * 2;
                    s_redc[warpM][cbase]     = crun[nj * 2 + 0];
                    s_redc[warpM][cbase + 1] = crun[nj * 2 + 1];
                }
            }
        }
        __syncthreads();

        if (tid < BM) {
            float2 m = s_redr[0][tid];
            top2_merge(m, s_redr[1][tid]);
            top2_merge(m, s_redr[2][tid]);
            top2_merge(m, s_redr[3][tid]);
            g_part[(size_t)(rowStart + tid) * NBLK + j] = m;
        }
        if (i != j && tid >= 128) {
            int c = tid - 128;
            float2 m = s_redc[0][c];
            top2_merge(m, s_redc[1][c]);
            g_part[(size_t)(colStart + c) * NBLK + i] = m;
        }

        i = i2; j = j2;
    }
}

// ---------------------------------------------------------------------------
// Kernel 3: merge 64 partials per row, compute losses/gates, final scalar
// ---------------------------------------------------------------------------
__global__ void __launch_bounds__(256) loss_kernel(float* __restrict__ out) {
    const int t = threadIdx.x;
    float sum_lg = 0.0f, sum_g = 0.0f;

    for (int r = t; r < NB; r += 256) {
        const float2* p = g_part + (size_t)r * NBLK;
        float2 m = p[0];
        #pragma unroll 8
        for (int b = 1; b < NBLK; b++) top2_merge(m, p[b]);
        float d2[2] = {m.x, m.y};
        #pragma unroll
        for (int e = 0; e < 2; e++) {
            float dist = sqrtf(fmaxf(2.0f - 2.0f * d2[e], 0.0f));
            float loss = -logf(dist + 1e-8f);
            float g    = 1.0f / (1.0f + expf(-(loss - 0.5f) * 10.0f));
            sum_lg += loss * g;
            sum_g  += g;
        }
    }
    #pragma unroll
    for (int o = 16; o > 0; o >>= 1) {
        sum_lg += __shfl_xor_sync(0xFFFFFFFFu, sum_lg, o);
        sum_g  += __shfl_xor_sync(0xFFFFFFFFu, sum_g,  o);
    }
    __shared__ float s_lg[8], s_g[8];
    int lane = t & 31, w = t >> 5;
    if (lane == 0) { s_lg[w] = sum_lg; s_g[w] = sum_g; }
    __syncthreads();
    if (t == 0) {
        float tl = 0.0f, tg = 0.0f;
        #pragma unroll
        for (int q = 0; q < 8; q++) { tl += s_lg[q]; tg += s_g[q]; }
        float weighted_mean = tl / (float)(NB * 2);
        float gated_mean    = tl / fmaxf(tg, 1.0f);
        out[0] = 0.5f * weighted_mean + 0.5f * gated_mean;
    }
}

// ---------------------------------------------------------------------------
extern "C" void kernel_launch(void* const* d_in, const int* in_sizes, int n_in,
                              void* d_out, int out_size) {
    const float* x = (const float*)d_in[0];
    float* out = (float*)d_out;

    normalize_kernel<<<NB, 256>>>(x);
    top2_sym_kernel<<<NCHUNKS, THREADS>>>();
    loss_kernel<<<1, 256>>>(out);
}

// round 7
// speedup vs baseline: 2.1977x; 2.1977x over previous
#include <cuda_runtime.h>
#include <cuda_fp16.h>
#include <cstdint>
#include <math.h>

#define NB 8192
#define ND 1024
#define BM 128
#define BN 128
#define BK 32
#define NBLK (NB / BM)                   /* 64 row/col blocks */
#define NTILES (NBLK * (NBLK + 1) / 2)   /* 2080 upper-tri tiles */
#define THREADS 256
#define LDS_PAD 40                       /* halves per smem row (80B stride) */
#define KBLOCKS (ND / BK)                /* 32 */
#define RED_BLOCKS 32

// ---------------- static device scratch (no allocation) --------------------
__device__ __half g_h[NB * ND];             // normalized rows fp16 (16 MB)
__device__ float2 g_part[NBLK * NB];        // [colblock][row] top-2 (4 MB)
__device__ float2 g_red[RED_BLOCKS];        // stage-1 partial (sum_lg, sum_g)

// ---------------- PTX helpers ----------------------------------------------
__device__ __forceinline__ uint32_t smem_u32(const void* p) {
    uint32_t a;
    asm("{ .reg .u64 t; cvta.to.shared.u64 t, %1; cvt.u32.u64 %0, t; }" : "=r"(a) : "l"(p));
    return a;
}
#define CP_ASYNC16(sm, gp) \
    asm volatile("cp.async.cg.shared.global [%0], [%1], 16;" :: "r"(sm), "l"(gp))
#define CP_COMMIT() asm volatile("cp.async.commit_group;" ::: "memory")
#define CP_WAIT1()  asm volatile("cp.async.wait_group 1;" ::: "memory")
#define CP_WAIT0()  asm volatile("cp.async.wait_group 0;" ::: "memory")
#define LDMATRIX_X4(r0, r1, r2, r3, addr) \
    asm volatile("ldmatrix.sync.aligned.m8n8.x4.shared.b16 {%0,%1,%2,%3}, [%4];" \
                 : "=r"(r0), "=r"(r1), "=r"(r2), "=r"(r3) : "r"(addr))
#define MMA16816(c, a, b0, b1) \
    asm volatile("mma.sync.aligned.m16n8k16.row.col.f32.f16.f16.f32 " \
                 "{%0,%1,%2,%3},{%4,%5,%6,%7},{%8,%9},{%0,%1,%2,%3};" \
                 : "+f"((c)[0]), "+f"((c)[1]), "+f"((c)[2]), "+f"((c)[3]) \
                 : "r"((a)[0]), "r"((a)[1]), "r"((a)[2]), "r"((a)[3]), "r"(b0), "r"(b1))

__device__ __forceinline__ void top2_merge(float2& t, float2 q) {
    if (q.x > t.x) { t.y = fmaxf(t.x, q.y); t.x = q.x; }
    else           { t.y = fmaxf(t.y, q.x); }
}
__device__ __forceinline__ void top2_push(float2& t, float v) {
    if (v > t.x) { t.y = t.x; t.x = v; }
    else if (v > t.y) { t.y = v; }
}
__device__ __forceinline__ void top2_shfl_merge(float2& t, int off) {
    float2 q;
    q.x = __shfl_xor_sync(0xFFFFFFFFu, t.x, off);
    q.y = __shfl_xor_sync(0xFFFFFFFFu, t.y, off);
    top2_merge(t, q);
}

// ---------------------------------------------------------------------------
// Kernel 1: L2-normalize rows, store fp16
// ---------------------------------------------------------------------------
__global__ void __launch_bounds__(256) normalize_kernel(const float* __restrict__ x) {
    int row = blockIdx.x;
    int t = threadIdx.x;
    const float4* xr = reinterpret_cast<const float4*>(x + (size_t)row * ND);
    float4 v = xr[t];
    float s = v.x * v.x + v.y * v.y + v.z * v.z + v.w * v.w;
    #pragma unroll
    for (int o = 16; o > 0; o >>= 1) s += __shfl_xor_sync(0xFFFFFFFFu, s, o);
    __shared__ float ws[8];
    int lane = t & 31, w = t >> 5;
    if (lane == 0) ws[w] = s;
    __syncthreads();
    if (t < 8) {
        float q = ws[t];
        #pragma unroll
        for (int o = 4; o > 0; o >>= 1) q += __shfl_xor_sync(0x000000FFu, q, o);
        if (t == 0) ws[0] = q;
    }
    __syncthreads();
    float inv = 1.0f / fmaxf(sqrtf(ws[0]), 1e-8f);
    __half2* oh = reinterpret_cast<__half2*>(g_h + (size_t)row * ND);
    oh[t * 2 + 0] = __floats2half2_rn(v.x * inv, v.y * inv);
    oh[t * 2 + 1] = __floats2half2_rn(v.z * inv, v.w * inv);
}

// ---------------------------------------------------------------------------
// Kernel 2: symmetric fp16 mma.sync — one upper-triangle 128x128 tile per CTA,
//           row-side then col-side top-2 reductions (sequential, low reg peak).
// ---------------------------------------------------------------------------
__global__ void __launch_bounds__(THREADS, 2) top2_sym_kernel() {
    __shared__ __half sA[2][BM * LDS_PAD];
    __shared__ __half sB[2][BN * LDS_PAD];
    __shared__ float2 s_redr[4][BM];   // row-side partials per N-warp
    __shared__ float2 s_redc[2][BN];   // col-side partials per M-warp

    // decode upper-triangle (i, j), i <= j
    int i = 0, base = 0;
    {
        const int idx = blockIdx.x;
        while (base + (NBLK - i) <= idx) { base += NBLK - i; ++i; }
        base = idx - base;
    }
    const int j = i + base;
    const int rowStart = i * BM;
    const int colStart = j * BN;

    const int tid = threadIdx.x;
    const int wid = tid >> 5, lane = tid & 31;
    const int warpM = wid >> 2, warpN = wid & 3;   // 2 x 4 warp grid

    const uint32_t sAu = smem_u32(&sA[0][0]);
    const uint32_t sBu = smem_u32(&sB[0][0]);
    const uint32_t BUFB = BM * LDS_PAD * 2;

    const int a_r = lane & 15;
    const int a_k = (lane >> 4) << 3;
    const int b_n = (lane & 7) + ((lane >> 4) << 3);
    const int b_k = ((lane >> 3) & 1) << 3;

    const int l_r0 = tid >> 2, l_k0 = tid & 3;
    const int l_r1 = (tid + 256) >> 2, l_k1 = (tid + 256) & 3;

    float acc[4][4][4];
    #pragma unroll
    for (int mi = 0; mi < 4; mi++)
        #pragma unroll
        for (int nj = 0; nj < 4; nj++)
            #pragma unroll
            for (int e = 0; e < 4; e++) acc[mi][nj][e] = 0.0f;

    // ---- prologue: stage 0 ----
    CP_ASYNC16(sAu + (l_r0 * LDS_PAD + l_k0 * 8) * 2,
               g_h + (size_t)(rowStart + l_r0) * ND + l_k0 * 8);
    CP_ASYNC16(sAu + (l_r1 * LDS_PAD + l_k1 * 8) * 2,
               g_h + (size_t)(rowStart + l_r1) * ND + l_k1 * 8);
    CP_ASYNC16(sBu + (l_r0 * LDS_PAD + l_k0 * 8) * 2,
               g_h + (size_t)(colStart + l_r0) * ND + l_k0 * 8);
    CP_ASYNC16(sBu + (l_r1 * LDS_PAD + l_k1 * 8) * 2,
               g_h + (size_t)(colStart + l_r1) * ND + l_k1 * 8);
    CP_COMMIT();

    for (int kb = 0; kb < KBLOCKS; kb++) {
        if (kb + 1 < KBLOCKS) {
            const int k0 = (kb + 1) * BK;
            const uint32_t bo = ((kb + 1) & 1) * BUFB;
            CP_ASYNC16(sAu + bo + (l_r0 * LDS_PAD + l_k0 * 8) * 2,
                       g_h + (size_t)(rowStart + l_r0) * ND + k0 + l_k0 * 8);
            CP_ASYNC16(sAu + bo + (l_r1 * LDS_PAD + l_k1 * 8) * 2,
                       g_h + (size_t)(rowStart + l_r1) * ND + k0 + l_k1 * 8);
            CP_ASYNC16(sBu + bo + (l_r0 * LDS_PAD + l_k0 * 8) * 2,
                       g_h + (size_t)(colStart + l_r0) * ND + k0 + l_k0 * 8);
            CP_ASYNC16(sBu + bo + (l_r1 * LDS_PAD + l_k1 * 8) * 2,
                       g_h + (size_t)(colStart + l_r1) * ND + k0 + l_k1 * 8);
            CP_COMMIT();
            CP_WAIT1();
        } else {
            CP_WAIT0();
        }
        __syncthreads();

        const uint32_t bo = (kb & 1) * BUFB;
        #pragma unroll
        for (int ks = 0; ks < 2; ks++) {
            uint32_t af[4][4];
            #pragma unroll
            for (int mi = 0; mi < 4; mi++) {
                uint32_t addr = sAu + bo +
                    ((warpM * 64 + mi * 16 + a_r) * LDS_PAD + ks * 16 + a_k) * 2;
                LDMATRIX_X4(af[mi][0], af[mi][1], af[mi][2], af[mi][3], addr);
            }
            uint32_t bf[2][4];
            #pragma unroll
            for (int nb = 0; nb < 2; nb++) {
                uint32_t addr = sBu + bo +
                    ((warpN * 32 + nb * 16 + b_n) * LDS_PAD + ks * 16 + b_k) * 2;
                LDMATRIX_X4(bf[nb][0], bf[nb][1], bf[nb][2], bf[nb][3], addr);
            }
            #pragma unroll
            for (int mi = 0; mi < 4; mi++)
                #pragma unroll
                for (int nj = 0; nj < 4; nj++)
                    MMA16816(acc[mi][nj], af[mi],
                             bf[nj >> 1][(nj & 1) * 2], bf[nj >> 1][(nj & 1) * 2 + 1]);
        }
        __syncthreads();
    }

    // ---- mask diagonal in-place (acc stays live through both phases) ----
    #pragma unroll
    for (int mi = 0; mi < 4; mi++) {
        const int row0 = rowStart + warpM * 64 + mi * 16 + (lane >> 2);
        #pragma unroll
        for (int nj = 0; nj < 4; nj++) {
            const int col0 = colStart + warpN * 32 + nj * 8 + (lane & 3) * 2;
            if (col0     == row0)     acc[mi][nj][0] = -2.0f;
            if (col0 + 1 == row0)     acc[mi][nj][1] = -2.0f;
            if (col0     == row0 + 8) acc[mi][nj][2] = -2.0f;
            if (col0 + 1 == row0 + 8) acc[mi][nj][3] = -2.0f;
        }
    }

    // ================= epilogue phase 1: row-side top-2 =================
    {
        float2 run[8];
        #pragma unroll
        for (int t2 = 0; t2 < 8; t2++) run[t2] = make_float2(-2.0f, -2.0f);

        #pragma unroll
        for (int mi = 0; mi < 4; mi++)
            #pragma unroll
            for (int nj = 0; nj < 4; nj++) {
                top2_push(run[mi * 2 + 0], acc[mi][nj][0]);
                top2_push(run[mi * 2 + 0], acc[mi][nj][1]);
                top2_push(run[mi * 2 + 1], acc[mi][nj][2]);
                top2_push(run[mi * 2 + 1], acc[mi][nj][3]);
            }

        #pragma unroll
        for (int t2 = 0; t2 < 8; t2++) {
            top2_shfl_merge(run[t2], 1);
            top2_shfl_merge(run[t2], 2);
        }
        if ((lane & 3) == 0) {
            #pragma unroll
            for (int mi = 0; mi < 4; mi++) {
                int rbase = warpM * 64 + mi * 16 + (lane >> 2);
                s_redr[warpN][rbase]     = run[mi * 2 + 0];
                s_redr[warpN][rbase + 8] = run[mi * 2 + 1];
            }
        }
    }

    // ================= epilogue phase 2: col-side top-2 =================
    if (i != j) {
        float2 crun[8];   // [nj][half]
        #pragma unroll
        for (int t2 = 0; t2 < 8; t2++) crun[t2] = make_float2(-2.0f, -2.0f);

        #pragma unroll
        for (int nj = 0; nj < 4; nj++)
            #pragma unroll
            for (int mi = 0; mi < 4; mi++) {
                top2_push(crun[nj * 2 + 0], acc[mi][nj][0]);
                top2_push(crun[nj * 2 + 1], acc[mi][nj][1]);
                top2_push(crun[nj * 2 + 0], acc[mi][nj][2]);
                top2_push(crun[nj * 2 + 1], acc[mi][nj][3]);
            }

        #pragma unroll
        for (int t2 = 0; t2 < 8; t2++) {
            top2_shfl_merge(crun[t2], 4);
            top2_shfl_merge(crun[t2], 8);
            top2_shfl_merge(crun[t2], 16);
        }
        if (lane < 4) {
            #pragma unroll
            for (int nj = 0; nj < 4; nj++) {
                int cbase = warpN * 32 + nj * 8 + lane * 2;
                s_redc[warpM][cbase]     = crun[nj * 2 + 0];
                s_redc[warpM][cbase + 1] = crun[nj * 2 + 1];
            }
        }
    }
    __syncthreads();

    // [blk][row] layout: coalesced writes
    if (tid < BM) {
        float2 m = s_redr[0][tid];
        top2_merge(m, s_redr[1][tid]);
        top2_merge(m, s_redr[2][tid]);
        top2_merge(m, s_redr[3][tid]);
        g_part[(size_t)j * NB + rowStart + tid] = m;
    }
    if (i != j && tid >= 128) {
        int c = tid - 128;
        float2 m = s_redc[0][c];
        top2_merge(m, s_redc[1][c]);
        g_part[(size_t)i * NB + colStart + c] = m;
    }
}

// ---------------------------------------------------------------------------
// Kernel 3a: parallel merge of 64 partials per row + loss/gate partial sums
// ---------------------------------------------------------------------------
__global__ void __launch_bounds__(256) loss_stage1_kernel() {
    const int r = blockIdx.x * 256 + threadIdx.x;   // one row per thread
    float2 m = g_part[r];
    #pragma unroll 8
    for (int b = 1; b < NBLK; b++) top2_merge(m, g_part[(size_t)b * NB + r]);

    float sum_lg = 0.0f, sum_g = 0.0f;
    float d2[2] = {m.x, m.y};
    #pragma unroll
    for (int e = 0; e < 2; e++) {
        float dist = sqrtf(fmaxf(2.0f - 2.0f * d2[e], 0.0f));
        float loss = -logf(dist + 1e-8f);
        float g    = 1.0f / (1.0f + expf(-(loss - 0.5f) * 10.0f));
        sum_lg += loss * g;
        sum_g  += g;
    }
    #pragma unroll
    for (int o = 16; o > 0; o >>= 1) {
        sum_lg += __shfl_xor_sync(0xFFFFFFFFu, sum_lg, o);
        sum_g  += __shfl_xor_sync(0xFFFFFFFFu, sum_g,  o);
    }
    __shared__ float s_lg[8], s_g[8];
    int lane = threadIdx.x & 31, w = threadIdx.x >> 5;
    if (lane == 0) { s_lg[w] = sum_lg; s_g[w] = sum_g; }
    __syncthreads();
    if (threadIdx.x == 0) {
        float tl = 0.0f, tg = 0.0f;
        #pragma unroll
        for (int q = 0; q < 8; q++) { tl += s_lg[q]; tg += s_g[q]; }
        g_red[blockIdx.x] = make_float2(tl, tg);
    }
}

// ---------------------------------------------------------------------------
// Kernel 3b: final scalar
// ---------------------------------------------------------------------------
__global__ void __launch_bounds__(32) loss_stage2_kernel(float* __restrict__ out) {
    const int t = threadIdx.x;
    float2 p = g_red[t];          // RED_BLOCKS == 32
    float tl = p.x, tg = p.y;
    #pragma unroll
    for (int o = 16; o > 0; o >>= 1) {
        tl += __shfl_xor_sync(0xFFFFFFFFu, tl, o);
        tg += __shfl_xor_sync(0xFFFFFFFFu, tg, o);
    }
    if (t == 0) {
        float weighted_mean = tl / (float)(NB * 2);
        float gated_mean    = tl / fmaxf(tg, 1.0f);
        out[0] = 0.5f * weighted_mean + 0.5f * gated_mean;
    }
}

// ---------------------------------------------------------------------------
extern "C" void kernel_launch(void* const* d_in, const int* in_sizes, int n_in,
                              void* d_out, int out_size) {
    const float* x = (const float*)d_in[0];
    float* out = (float*)d_out;

    normalize_kernel<<<NB, 256>>>(x);
    top2_sym_kernel<<<NTILES, THREADS>>>();
    loss_stage1_kernel<<<RED_BLOCKS, 256>>>();
    loss_stage2_kernel<<<1, 32>>>(out);
}